// round 5
// baseline (speedup 1.0000x reference)
#include <cuda_runtime.h>
#include <cuda_bf16.h>

// Problem constants
#define NG        2048      // glimpses
#define NPG       512       // points per glimpse
#define CPG       128       // level-1 clusters per glimpse
#define CPG2      32        // level-2 clusters per glimpse

__device__ __forceinline__ float celu1(float x) { return x > 0.f ? x : expm1f(x); }

// scratch: per-glimpse stage-3 mean features [NG][128]  (1 MB)
__device__ float g_agg3m[NG * 128];

// ---------------------------------------------------------------------------
// Kernel A: one CTA per glimpse. Fuses:
//   stage1 edge-MLP (512 pts, 4->16) + seg-mean(128) + f1 = celu(agg@W1g+b1g) (16->32)
//   stage2 edge-MLP (128 rows, 35->64) + seg-mean(32) + f2 = celu(agg@W2g+b2g) (64->128)
//   stage3 edge-MLP (32 rows, 131->128) + mean(32)  -> g_agg3m
// All intermediates live in shared memory (overlapped regions, 38.7 KB).
// ---------------------------------------------------------------------------
__global__ __launch_bounds__(256, 4) void glimpse_kernel(
    const float* __restrict__ rgb,  const float* __restrict__ pos,
    const float* __restrict__ pos1, const float* __restrict__ pos2,
    const int* __restrict__ idx0, const int* __restrict__ idx1,
    const float* __restrict__ W1l, const float* __restrict__ b1l,
    const float* __restrict__ W1g, const float* __restrict__ b1g,
    const float* __restrict__ W2l, const float* __restrict__ b2l,
    const float* __restrict__ W2g, const float* __restrict__ b2g,
    const float* __restrict__ W3l, const float* __restrict__ b3l)
{
    __shared__ __align__(16) float smem[9664];   // 38656 bytes

    // persistent regions
    float* pos1L = smem;            // [128*3]
    float* pos2L = smem + 384;      // [32*3]
    float* b2gS  = smem + 480;      // [128]
    float* b3lS  = smem + 608;      // [128]
    float* agg3  = smem + 736;      // [128]
    float* cnt1  = smem + 864;      // [128]
    float* cnt2  = smem + 992;      // [32]
    // overlapped regions
    float* R1 = smem + 1024;        // 2304 floats: agg1[128][17]  -> W2l[35][64]+b2l[64]
    float* R2 = smem + 3328;        // 2112 floats: W1 weights     -> agg2[32][65]
    float* R3 = smem + 5440;        // 4224 floats: f1[128][33]    -> f2[32][129]

    const int t = threadIdx.x;
    const int g = blockIdx.x;

    // ---- phase 0: loads + zeroing ----
    float* agg1 = R1;                          // [128][17] padded
    float* W1lS = R2;                          // [4][16]
    float* b1lS = R2 + 64;                     // [16]
    float* W1gS = R2 + 80;                     // [16][32]
    float* b1gS = R2 + 592;                    // [32]
    float* f1   = R3;                          // [128][33] padded

    for (int i = t; i < 384; i += 256) pos1L[i] = pos1[g * 384 + i];
    for (int i = t; i < 96;  i += 256) pos2L[i] = pos2[g * 96 + i];
    for (int i = t; i < 128; i += 256) {
        b2gS[i] = b2g[i]; b3lS[i] = b3l[i];
        agg3[i] = 0.f; cnt1[i] = 0.f;
    }
    if (t < 32) cnt2[t] = 0.f;
    for (int i = t; i < 128 * 17; i += 256) agg1[i] = 0.f;
    if (t < 64) W1lS[t] = W1l[t];
    if (t < 16) b1lS[t] = b1l[t];
    for (int i = t; i < 512; i += 256) W1gS[i] = W1g[i];
    if (t < 32) b1gS[t] = b1g[t];
    __syncthreads();

    // ---- phase 1: edge MLP (4->16) + shared-atomic segment sum ----
    for (int p = t; p < NPG; p += 256) {
        const int gp = g * NPG + p;
        const float x0 = rgb[gp];
        const int s = ((int)idx0[gp] - g * CPG) & (CPG - 1);   // 0..127 (masked safe)
        const float rx = pos[gp * 3 + 0] - pos1L[s * 3 + 0];
        const float ry = pos[gp * 3 + 1] - pos1L[s * 3 + 1];
        const float rz = pos[gp * 3 + 2] - pos1L[s * 3 + 2];
        float* base = &agg1[s * 17];
        #pragma unroll
        for (int j = 0; j < 16; j++) {
            float h = b1lS[j] + x0 * W1lS[j] + rx * W1lS[16 + j]
                              + ry * W1lS[32 + j] + rz * W1lS[48 + j];
            atomicAdd(&base[j], celu1(h));
        }
        atomicAdd(&cnt1[s], 1.f);
    }
    __syncthreads();

    // normalize agg1 by counts
    for (int i = t; i < 2048; i += 256) {
        int s = i >> 4, j = i & 15;
        agg1[s * 17 + j] *= 1.f / fmaxf(cnt1[s], 1.f);
    }
    __syncthreads();

    // f1 = celu(agg1 @ W1g + b1g)  [128][32]
    for (int i = t; i < 4096; i += 256) {
        int s = i >> 5, o = i & 31;
        float acc = b1gS[o];
        const float* a = &agg1[s * 17];
        #pragma unroll
        for (int j = 0; j < 16; j++) acc += a[j] * W1gS[j * 32 + o];
        f1[s * 33 + o] = celu1(acc);
    }
    __syncthreads();

    // ---- phase 2 prep: R1 -> W2l, R2 -> agg2 ----
    float* W2lS = R1;                          // [35][64]
    float* b2lS = R1 + 2240;                   // [64]
    float* agg2 = R2;                          // [32][65] padded
    float* f2   = R3;                          // [32][129] padded (overlays f1 later)

    for (int i = t; i < 2240; i += 256) W2lS[i] = W2l[i];
    if (t < 64) b2lS[t] = b2l[t];
    for (int i = t; i < 32 * 65; i += 256) agg2[i] = 0.f;
    __syncthreads();

    // ---- phase 2 edges: 128 rows, 2 threads/row, 32 outputs each ----
    {
        const int r  = t >> 1;
        const int ho = (t & 1) * 32;
        const int gi = g * CPG + r;
        const int s  = ((int)idx1[gi] - g * CPG2) & (CPG2 - 1);   // 0..31 (masked safe)
        float acc[32];
        #pragma unroll
        for (int o = 0; o < 32; o++) acc[o] = b2lS[ho + o];
        #pragma unroll 4
        for (int k = 0; k < 32; k++) {
            const float xv = f1[r * 33 + k];
            const float* wrow = &W2lS[k * 64 + ho];
            #pragma unroll
            for (int o = 0; o < 32; o++) acc[o] += xv * wrow[o];
        }
        const float rel[3] = { pos1L[r * 3 + 0] - pos2L[s * 3 + 0],
                               pos1L[r * 3 + 1] - pos2L[s * 3 + 1],
                               pos1L[r * 3 + 2] - pos2L[s * 3 + 2] };
        #pragma unroll
        for (int k = 0; k < 3; k++) {
            const float* wrow = &W2lS[(32 + k) * 64 + ho];
            #pragma unroll
            for (int o = 0; o < 32; o++) acc[o] += rel[k] * wrow[o];
        }
        float* abase = &agg2[s * 65 + ho];
        #pragma unroll
        for (int o = 0; o < 32; o++) atomicAdd(&abase[o], celu1(acc[o]));
        if ((t & 1) == 0) atomicAdd(&cnt2[s], 1.f);
    }
    __syncthreads();

    // normalize agg2
    for (int i = t; i < 2048; i += 256) {
        int s = i >> 6, j = i & 63;
        agg2[s * 65 + j] *= 1.f / fmaxf(cnt2[s], 1.f);
    }
    __syncthreads();

    // f2 = celu(agg2 @ W2g + b2g)  [32][128]; W2g streamed from L2, register-tiled
    {
        const int o  = t & 127;
        const int sb = (t >> 7) * 16;
        float acc[16];
        const float bo = b2gS[o];
        #pragma unroll
        for (int r = 0; r < 16; r++) acc[r] = bo;
        for (int j = 0; j < 64; j++) {
            const float w = W2g[j * 128 + o];
            #pragma unroll
            for (int r = 0; r < 16; r++) acc[r] += agg2[(sb + r) * 65 + j] * w;
        }
        #pragma unroll
        for (int r = 0; r < 16; r++) f2[(sb + r) * 129 + o] = celu1(acc[r]);
    }
    __syncthreads();

    // ---- phase 3 edges: 32 rows, 131 -> 128, then mean over rows ----
    {
        const int k  = t & 127;
        const int rb = (t >> 7) * 16;
        float acc[16];
        #pragma unroll
        for (int r = 0; r < 16; r++) acc[r] = 0.f;
        for (int i = 0; i < 128; i++) {
            const float w = W3l[i * 128 + k];
            #pragma unroll
            for (int r = 0; r < 16; r++) acc[r] += f2[(rb + r) * 129 + i] * w;
        }
        #pragma unroll
        for (int i = 0; i < 3; i++) {
            const float w = W3l[(128 + i) * 128 + k];
            #pragma unroll
            for (int r = 0; r < 16; r++) acc[r] += pos2L[(rb + r) * 3 + i] * w;
        }
        const float bk = b3lS[k];
        float sum = 0.f;
        #pragma unroll
        for (int r = 0; r < 16; r++) sum += celu1(acc[r] + bk);
        atomicAdd(&agg3[k], sum);
    }
    __syncthreads();

    if (t < 128) g_agg3m[g * 128 + t] = agg3[t] * (1.f / 32.f);
}

// ---------------------------------------------------------------------------
// Kernel B: tail. 16 glimpses per CTA so W3g/Wlin are read once per CTA.
//   f3 = celu(agg3m @ W3g + b3g)   (128->256)   -> out region 4
//   o  = f3 @ Wlin + blin ; mu/sg split; sigma=softplus; z = mu + sigma*eps
// ---------------------------------------------------------------------------
#define GPB 16
__global__ __launch_bounds__(256, 4) void tail_kernel(
    const float* __restrict__ W3g, const float* __restrict__ b3g,
    const float* __restrict__ Wlin, const float* __restrict__ blin,
    const float* __restrict__ eps, float* __restrict__ out)
{
    __shared__ float sA[GPB * 128];   // agg3m tile
    __shared__ float sF[GPB * 256];   // f3 tile
    __shared__ float sO[GPB * 256];   // linear output tile

    const int t  = threadIdx.x;
    const int g0 = blockIdx.x * GPB;

    for (int i = t; i < GPB * 128; i += 256) sA[i] = g_agg3m[g0 * 128 + i];
    __syncthreads();

    const int o = t;   // 0..255
    {
        float acc[GPB];
        const float bo = b3g[o];
        #pragma unroll
        for (int r = 0; r < GPB; r++) acc[r] = bo;
        for (int j = 0; j < 128; j++) {
            const float w = W3g[j * 256 + o];
            #pragma unroll
            for (int r = 0; r < GPB; r++) acc[r] += sA[r * 128 + j] * w;
        }
        #pragma unroll
        for (int r = 0; r < GPB; r++) {
            const float v = celu1(acc[r]);
            sF[r * 256 + o] = v;
            out[786432 + (size_t)(g0 + r) * 256 + o] = v;   // "f" output
        }
    }
    __syncthreads();
    {
        float acc[GPB];
        const float bo = blin[o];
        #pragma unroll
        for (int r = 0; r < GPB; r++) acc[r] = bo;
        for (int j = 0; j < 256; j++) {
            const float w = Wlin[j * 256 + o];
            #pragma unroll
            for (int r = 0; r < GPB; r++) acc[r] += sF[r * 256 + j] * w;
        }
        #pragma unroll
        for (int r = 0; r < GPB; r++) sO[r * 256 + o] = acc[r];
    }
    __syncthreads();

    for (int i = t; i < GPB * 128; i += 256) {
        const int r = i >> 7, c = i & 127;
        const int gid = g0 + r;
        const float mu = sO[r * 256 + c];
        const float sg = sO[r * 256 + 128 + c];
        const float sigma = (sg > 20.f) ? sg : log1pf(expf(sg));
        const float z = mu + sigma * eps[gid * 128 + c];
        if (c < 64) out[(size_t)gid * 64 + c] = z;                      // z_what
        else        out[131072 + (size_t)gid * 64 + (c - 64)] = z;      // z_mask
        out[262144 + (size_t)gid * 128 + c] = mu;                       // mu
        out[524288 + (size_t)gid * 128 + c] = sigma;                    // sigma
    }
}

extern "C" void kernel_launch(void* const* d_in, const int* in_sizes, int n_in,
                              void* d_out, int out_size)
{
    (void)in_sizes; (void)n_in; (void)out_size;
    const float* rgb  = (const float*)d_in[0];
    const float* pos  = (const float*)d_in[1];
    const float* pos1 = (const float*)d_in[2];
    const float* pos2 = (const float*)d_in[3];
    const int*   idx0 = (const int*)d_in[4];
    const int*   idx1 = (const int*)d_in[5];
    // d_in[6] (out_index2) unused: structure is implied (32 pts/glimpse)
    const float* eps  = (const float*)d_in[7];
    const float* W1l  = (const float*)d_in[8];
    const float* b1l  = (const float*)d_in[9];
    const float* W1g  = (const float*)d_in[10];
    const float* b1g  = (const float*)d_in[11];
    const float* W2l  = (const float*)d_in[12];
    const float* b2l  = (const float*)d_in[13];
    const float* W2g  = (const float*)d_in[14];
    const float* b2g  = (const float*)d_in[15];
    const float* W3l  = (const float*)d_in[16];
    const float* b3l  = (const float*)d_in[17];
    const float* W3g  = (const float*)d_in[18];
    const float* b3g  = (const float*)d_in[19];
    const float* Wlin = (const float*)d_in[20];
    const float* blin = (const float*)d_in[21];
    float* out = (float*)d_out;

    glimpse_kernel<<<NG, 256>>>(rgb, pos, pos1, pos2, idx0, idx1,
                                W1l, b1l, W1g, b1g, W2l, b2l, W2g, b2g, W3l, b3l);
    tail_kernel<<<NG / GPB, 256>>>(W3g, b3g, Wlin, blin, eps, out);
}

// round 6
// speedup vs baseline: 2.5695x; 2.5695x over previous
#include <cuda_runtime.h>
#include <cuda_bf16.h>

// Problem constants
#define NG        2048      // glimpses
#define NPG       512       // points per glimpse
#define CPG       128       // level-1 clusters per glimpse
#define CPG2      32        // level-2 clusters per glimpse

__device__ __forceinline__ float celu1(float x) { return x > 0.f ? x : expm1f(x); }

// scratch: per-glimpse stage-3 mean features [NG][128]  (1 MB)
__device__ float g_agg3m[NG * 128];

// ---------------------------------------------------------------------------
// Shared-memory layout (floats), total 14024 floats = 56096 B -> occ 4
//   misc block [0..2384) incl. int arrays
//   A = 2384 : xT[35][132]  (k-major X for phase-2 edge; rows 0..31 = f1T,
//              rows 32..34 = rel). Earlier in time: point staging + plist.
//   D = 7004 : agg2T[64][36]  (j-major level-2 aggregate)
//   C = 9308 : agg1T[16][132] @C + W2lS[35][64] @C+2112  -> later f2T[131][36]
// ---------------------------------------------------------------------------
#define OFF_POS1   0      // 384
#define OFF_POS2   384    // 96
#define OFF_W1L    480    // 64
#define OFF_B1L    544    // 16
#define OFF_W1G    560    // 512
#define OFF_B1G    1072   // 32
#define OFF_B2L    1104   // 64
#define OFF_B2G    1168   // 128
#define OFF_B3L    1296   // 128
#define OFF_AGG3   1424   // 128
#define OFF_S1     1552   // 128 int
#define OFF_SLOT   1680   // 128 int
#define OFF_SSEG   1808   // 128 int
#define OFF_OFF1   1936   // 128 int
#define OFF_OFF1F  2064   // 128 int
#define OFF_OFF2F  2192   // 32  int
#define OFF_CNT1   2224   // 128 int
#define OFF_CNT2   2352   // 32  int
#define OFF_A      2384   // 4620
#define OFF_D      7004   // 2304
#define OFF_C      9308   // 4716
#define SMEM_TOT   14024

__global__ __launch_bounds__(256, 4) void glimpse_kernel(
    const float* __restrict__ rgb,  const float* __restrict__ pos,
    const float* __restrict__ pos1, const float* __restrict__ pos2,
    const int* __restrict__ idx0, const int* __restrict__ idx1,
    const float* __restrict__ W1l, const float* __restrict__ b1l,
    const float* __restrict__ W1g, const float* __restrict__ b1g,
    const float* __restrict__ W2l, const float* __restrict__ b2l,
    const float* __restrict__ W2g, const float* __restrict__ b2g,
    const float* __restrict__ W3l, const float* __restrict__ b3l)
{
    __shared__ __align__(16) float sm[SMEM_TOT];
    int* smi = (int*)sm;

    float* pos1L = sm + OFF_POS1;
    float* pos2L = sm + OFF_POS2;
    float* W1lS  = sm + OFF_W1L;
    float* b1lS  = sm + OFF_B1L;
    float* W1gS  = sm + OFF_W1G;
    float* b1gS  = sm + OFF_B1G;
    float* b2lS  = sm + OFF_B2L;
    float* b2gS  = sm + OFF_B2G;
    float* b3lS  = sm + OFF_B3L;
    float* agg3  = sm + OFF_AGG3;
    int*   s1    = smi + OFF_S1;
    int*   slot  = smi + OFF_SLOT;
    int*   sseg  = smi + OFF_SSEG;
    int*   off1  = smi + OFF_OFF1;
    int*   off1f = smi + OFF_OFF1F;
    int*   off2f = smi + OFF_OFF2F;
    int*   cnt1i = smi + OFF_CNT1;
    int*   cnt2i = smi + OFF_CNT2;

    float* xT    = sm + OFF_A;            // [35][132]
    float* stX   = sm + OFF_A;            // [512]   staging (dead before xT written)
    float* stPx  = sm + OFF_A + 512;      // [512]
    float* stPy  = sm + OFF_A + 1024;     // [512]
    float* stPz  = sm + OFF_A + 1536;     // [512]
    int*   stS   = smi + OFF_A + 2048;    // [512]
    int*   plist = smi + OFF_A + 2560;    // [512]
    float* agg2T = sm + OFF_D;            // [64][36]
    float* agg1T = sm + OFF_C;            // [16][132]
    float* W2lS  = sm + OFF_C + 2112;     // [35][64]
    float* f2T   = sm + OFF_C;            // [131][36] (overwrites agg1T/W2lS later)

    const int t = threadIdx.x;
    const int g = blockIdx.x;

    // ---- block 0: loads + zeros ----
    for (int i = t; i < 384; i += 256) pos1L[i] = pos1[g * 384 + i];
    for (int i = t; i < 96;  i += 256) pos2L[i] = pos2[g * 96 + i];
    if (t < 64) { W1lS[t] = W1l[t]; b2lS[t] = b2l[t]; }
    if (t < 16) b1lS[t] = b1l[t];
    for (int i = t; i < 512; i += 256) W1gS[i] = W1g[i];
    if (t < 32) b1gS[t] = b1g[t];
    for (int i = t; i < 128; i += 256) { b2gS[i] = b2g[i]; b3lS[i] = b3l[i]; agg3[i] = 0.f; cnt1i[i] = 0; }
    if (t < 32) cnt2i[t] = 0;
    for (int i = t; i < 2112; i += 256) agg1T[i] = 0.f;
    for (int i = t; i < 2304; i += 256) agg2T[i] = 0.f;
    for (int i = t; i < 2240; i += 256) W2lS[i] = W2l[i];
    __syncthreads();

    // ---- block 1: stage points + counts ----
    for (int p = t; p < 512; p += 256) {
        stX[p] = rgb[g * 512 + p];
        int s = (idx0[g * 512 + p] - g * CPG) & (CPG - 1);
        stS[p] = s;
        atomicAdd(&cnt1i[s], 1);
    }
    for (int i = t; i < 1536; i += 256) {
        float v = pos[g * 1536 + i];
        int p = i / 3, c = i - p * 3;
        if (c == 0) stPx[p] = v; else if (c == 1) stPy[p] = v; else stPz[p] = v;
    }
    if (t < 128) {
        int s = (idx1[g * 128 + t] - g * CPG2) & (CPG2 - 1);
        s1[t] = s;
        atomicAdd(&cnt2i[s], 1);
    }
    __syncthreads();

    // ---- block 2: prefix sums (warp0: 128 seg counts; warp1: 32) ----
    if (t < 32) {
        int carry = 0;
        for (int c = 0; c < 4; c++) {
            int v = cnt1i[c * 32 + t];
            int x = v;
            #pragma unroll
            for (int d = 1; d < 32; d <<= 1) {
                int y = __shfl_up_sync(0xffffffffu, x, d);
                if (t >= d) x += y;
            }
            int excl = x - v + carry;
            off1[c * 32 + t] = excl;
            off1f[c * 32 + t] = excl;
            carry += __shfl_sync(0xffffffffu, x, 31);
        }
    } else if (t < 64) {
        int lane = t - 32;
        int v = cnt2i[lane];
        int x = v;
        #pragma unroll
        for (int d = 1; d < 32; d <<= 1) {
            int y = __shfl_up_sync(0xffffffffu, x, d);
            if (lane >= d) x += y;
        }
        off2f[lane] = x - v;
    }
    __syncthreads();

    // ---- block 3: scatter point list + row slots ----
    for (int p = t; p < 512; p += 256) {
        int s = stS[p];
        int pp = atomicAdd(&off1f[s], 1);
        plist[pp] = p;
    }
    if (t < 128) {
        int s = s1[t];
        int q = atomicAdd(&off2f[s], 1);
        slot[t] = q;
        sseg[q] = s;
    }
    __syncthreads();

    // ---- block 4: phase-1 accumulate (no feature atomics) + rel rows ----
    {
        int s = t >> 1, jb = (t & 1) * 8;
        int cnt = cnt1i[s], base = off1[s];
        float acc[8];
        #pragma unroll
        for (int j = 0; j < 8; j++) acc[j] = 0.f;
        const float c1x = pos1L[s * 3 + 0], c1y = pos1L[s * 3 + 1], c1z = pos1L[s * 3 + 2];
        for (int e = 0; e < cnt; e++) {
            int p = plist[base + e];
            float x0 = stX[p];
            float rx = stPx[p] - c1x, ry = stPy[p] - c1y, rz = stPz[p] - c1z;
            #pragma unroll
            for (int j = 0; j < 8; j++) {
                float h = b1lS[jb + j] + x0 * W1lS[jb + j] + rx * W1lS[16 + jb + j]
                        + ry * W1lS[32 + jb + j] + rz * W1lS[48 + jb + j];
                acc[j] += celu1(h);
            }
        }
        float inv = 1.f / (float)max(cnt, 1);
        #pragma unroll
        for (int j = 0; j < 8; j++) agg1T[(jb + j) * 132 + s] = acc[j] * inv;
    }
    for (int i = t; i < 384; i += 256) {
        int c = i >> 7, r = i & 127;
        int q = slot[r], s = s1[r];
        xT[(32 + c) * 132 + q] = pos1L[r * 3 + c] - pos2L[s * 3 + c];
    }
    __syncthreads();

    // ---- f1 GEMM: [128r x 16j] @ [16j x 32o] -> xT rows 0..31 at sorted slots
    {
        int ob = t & 7, rb = t >> 3;
        int r0 = rb * 4, o0 = ob * 4;
        float acc[4][4];
        #pragma unroll
        for (int ri = 0; ri < 4; ri++)
            #pragma unroll
            for (int oi = 0; oi < 4; oi++) acc[ri][oi] = b1gS[o0 + oi];
        #pragma unroll
        for (int j = 0; j < 16; j++) {
            float4 x = *(const float4*)&agg1T[j * 132 + r0];
            float4 w = *(const float4*)&W1gS[j * 32 + o0];
            float xa[4] = {x.x, x.y, x.z, x.w};
            float wa[4] = {w.x, w.y, w.z, w.w};
            #pragma unroll
            for (int ri = 0; ri < 4; ri++)
                #pragma unroll
                for (int oi = 0; oi < 4; oi++) acc[ri][oi] += xa[ri] * wa[oi];
        }
        int sl[4];
        #pragma unroll
        for (int ri = 0; ri < 4; ri++) sl[ri] = slot[r0 + ri];
        #pragma unroll
        for (int ri = 0; ri < 4; ri++)
            #pragma unroll
            for (int oi = 0; oi < 4; oi++)
                xT[(o0 + oi) * 132 + sl[ri]] = celu1(acc[ri][oi]);
    }
    __syncthreads();

    // ---- phase-2 edge GEMM: 128 rows (sorted) x [35 -> 64], run-merged atomics
    {
        int ob = t & 15, rb = t >> 4;
        int q0 = rb * 8, o0 = ob * 4;
        float acc[8][4];
        #pragma unroll
        for (int i = 0; i < 8; i++)
            #pragma unroll
            for (int oi = 0; oi < 4; oi++) acc[i][oi] = b2lS[o0 + oi];
        #pragma unroll 5
        for (int k = 0; k < 35; k++) {
            float4 xa4 = *(const float4*)&xT[k * 132 + q0];
            float4 xb4 = *(const float4*)&xT[k * 132 + q0 + 4];
            float4 w4  = *(const float4*)&W2lS[k * 64 + o0];
            float xa[8] = {xa4.x, xa4.y, xa4.z, xa4.w, xb4.x, xb4.y, xb4.z, xb4.w};
            float wa[4] = {w4.x, w4.y, w4.z, w4.w};
            #pragma unroll
            for (int i = 0; i < 8; i++)
                #pragma unroll
                for (int oi = 0; oi < 4; oi++) acc[i][oi] += xa[i] * wa[oi];
        }
        float run[4] = {0.f, 0.f, 0.f, 0.f};
        int curS = sseg[q0];
        #pragma unroll
        for (int i = 0; i < 8; i++) {
            int s = sseg[q0 + i];
            if (s != curS) {
                #pragma unroll
                for (int oi = 0; oi < 4; oi++) {
                    atomicAdd(&agg2T[(o0 + oi) * 36 + curS], run[oi]);
                    run[oi] = 0.f;
                }
                curS = s;
            }
            #pragma unroll
            for (int oi = 0; oi < 4; oi++) run[oi] += celu1(acc[i][oi]);
        }
        #pragma unroll
        for (int oi = 0; oi < 4; oi++) atomicAdd(&agg2T[(o0 + oi) * 36 + curS], run[oi]);
    }
    __syncthreads();

    // normalize agg2T
    for (int i = t; i < 2048; i += 256) {
        int j = i >> 5, s = i & 31;
        agg2T[j * 36 + s] *= 1.f / fmaxf((float)cnt2i[s], 1.f);
    }
    __syncthreads();

    // ---- f2 GEMM: [32s x 64j] @ W2g[64 x 128] -> f2T[128][32] (+pos2 rows)
    {
        int ob = t & 31, sb = t >> 5;
        int s0 = sb * 4, o0 = ob * 4;
        float acc[4][4];
        #pragma unroll
        for (int si = 0; si < 4; si++)
            #pragma unroll
            for (int oi = 0; oi < 4; oi++) acc[si][oi] = b2gS[o0 + oi];
        #pragma unroll 4
        for (int j = 0; j < 64; j++) {
            float4 x = *(const float4*)&agg2T[j * 36 + s0];
            float4 w = *(const float4*)&W2g[j * 128 + o0];
            float xa[4] = {x.x, x.y, x.z, x.w};
            float wa[4] = {w.x, w.y, w.z, w.w};
            #pragma unroll
            for (int si = 0; si < 4; si++)
                #pragma unroll
                for (int oi = 0; oi < 4; oi++) acc[si][oi] += xa[si] * wa[oi];
        }
        #pragma unroll
        for (int oi = 0; oi < 4; oi++)
            #pragma unroll
            for (int si = 0; si < 4; si++)
                f2T[(o0 + oi) * 36 + s0 + si] = celu1(acc[si][oi]);
    }
    if (t < 96) {
        int c = t >> 5, s = t & 31;
        f2T[(128 + c) * 36 + s] = pos2L[s * 3 + c];
    }
    __syncthreads();

    // ---- phase-3 GEMM: [32s x 131i] @ W3l[131 x 128] -> celu -> col-mean
    {
        int kb = t & 31, srb = t >> 5;
        int s0 = srb * 4, k0 = kb * 4;
        float acc[4][4];
        #pragma unroll
        for (int si = 0; si < 4; si++)
            #pragma unroll
            for (int ki = 0; ki < 4; ki++) acc[si][ki] = 0.f;
        #pragma unroll 4
        for (int i = 0; i < 131; i++) {
            float4 x = *(const float4*)&f2T[i * 36 + s0];
            float4 w = *(const float4*)&W3l[i * 128 + k0];
            float xa[4] = {x.x, x.y, x.z, x.w};
            float wa[4] = {w.x, w.y, w.z, w.w};
            #pragma unroll
            for (int si = 0; si < 4; si++)
                #pragma unroll
                for (int ki = 0; ki < 4; ki++) acc[si][ki] += xa[si] * wa[ki];
        }
        float part[4] = {0.f, 0.f, 0.f, 0.f};
        #pragma unroll
        for (int si = 0; si < 4; si++)
            #pragma unroll
            for (int ki = 0; ki < 4; ki++)
                part[ki] += celu1(acc[si][ki] + b3lS[k0 + ki]);
        #pragma unroll
        for (int ki = 0; ki < 4; ki++) atomicAdd(&agg3[k0 + ki], part[ki]);
    }
    __syncthreads();

    if (t < 128) g_agg3m[g * 128 + t] = agg3[t] * (1.f / 32.f);
}

// ---------------------------------------------------------------------------
// Tail: GPB=8 glimpses per CTA -> grid 256 (full chip), register tile of 8.
//   f3 = celu(agg3m @ W3g + b3g); o = f3 @ Wlin + blin; split/softplus/sample.
// ---------------------------------------------------------------------------
#define GPB 8
__global__ __launch_bounds__(256) void tail_kernel(
    const float* __restrict__ W3g, const float* __restrict__ b3g,
    const float* __restrict__ Wlin, const float* __restrict__ blin,
    const float* __restrict__ eps, float* __restrict__ out)
{
    __shared__ __align__(16) float sAT[128 * GPB];   // [j][g]
    __shared__ __align__(16) float sFT[256 * GPB];   // [j][g]
    __shared__ __align__(16) float sO[256 * GPB];    // [o][g]

    const int t  = threadIdx.x;
    const int g0 = blockIdx.x * GPB;

    for (int i = t; i < 128 * GPB; i += 256) {
        int j = i >> 3, gg = i & 7;
        sAT[j * 8 + gg] = g_agg3m[(g0 + gg) * 128 + j];
    }
    __syncthreads();

    const int o = t;
    {
        float acc[8];
        const float bo = b3g[o];
        #pragma unroll
        for (int gg = 0; gg < 8; gg++) acc[gg] = bo;
        #pragma unroll 4
        for (int j = 0; j < 128; j++) {
            const float w = W3g[j * 256 + o];
            float4 a0 = *(const float4*)&sAT[j * 8];
            float4 a1 = *(const float4*)&sAT[j * 8 + 4];
            acc[0] += a0.x * w; acc[1] += a0.y * w; acc[2] += a0.z * w; acc[3] += a0.w * w;
            acc[4] += a1.x * w; acc[5] += a1.y * w; acc[6] += a1.z * w; acc[7] += a1.w * w;
        }
        #pragma unroll
        for (int gg = 0; gg < 8; gg++) {
            float v = celu1(acc[gg]);
            sFT[o * 8 + gg] = v;
            out[786432 + (size_t)(g0 + gg) * 256 + o] = v;   // "f" output
        }
    }
    __syncthreads();
    {
        float acc[8];
        const float bo = blin[o];
        #pragma unroll
        for (int gg = 0; gg < 8; gg++) acc[gg] = bo;
        #pragma unroll 4
        for (int j = 0; j < 256; j++) {
            const float w = Wlin[j * 256 + o];
            float4 a0 = *(const float4*)&sFT[j * 8];
            float4 a1 = *(const float4*)&sFT[j * 8 + 4];
            acc[0] += a0.x * w; acc[1] += a0.y * w; acc[2] += a0.z * w; acc[3] += a0.w * w;
            acc[4] += a1.x * w; acc[5] += a1.y * w; acc[6] += a1.z * w; acc[7] += a1.w * w;
        }
        #pragma unroll
        for (int gg = 0; gg < 8; gg++) sO[o * 8 + gg] = acc[gg];
    }
    __syncthreads();

    for (int i = t; i < 128 * GPB; i += 256) {
        int gg = i >> 7, c = i & 127;
        int gid = g0 + gg;
        float mu = sO[c * 8 + gg];
        float sg = sO[(128 + c) * 8 + gg];
        float sigma = (sg > 20.f) ? sg : log1pf(expf(sg));
        float z = mu + sigma * eps[gid * 128 + c];
        if (c < 64) out[(size_t)gid * 64 + c] = z;                      // z_what
        else        out[131072 + (size_t)gid * 64 + (c - 64)] = z;      // z_mask
        out[262144 + (size_t)gid * 128 + c] = mu;                       // mu
        out[524288 + (size_t)gid * 128 + c] = sigma;                    // sigma
    }
}

extern "C" void kernel_launch(void* const* d_in, const int* in_sizes, int n_in,
                              void* d_out, int out_size)
{
    (void)in_sizes; (void)n_in; (void)out_size;
    const float* rgb  = (const float*)d_in[0];
    const float* pos  = (const float*)d_in[1];
    const float* pos1 = (const float*)d_in[2];
    const float* pos2 = (const float*)d_in[3];
    const int*   idx0 = (const int*)d_in[4];
    const int*   idx1 = (const int*)d_in[5];
    // d_in[6] (out_index2) unused: structure is implied (32 pts/glimpse)
    const float* eps  = (const float*)d_in[7];
    const float* W1l  = (const float*)d_in[8];
    const float* b1l  = (const float*)d_in[9];
    const float* W1g  = (const float*)d_in[10];
    const float* b1g  = (const float*)d_in[11];
    const float* W2l  = (const float*)d_in[12];
    const float* b2l  = (const float*)d_in[13];
    const float* W2g  = (const float*)d_in[14];
    const float* b2g  = (const float*)d_in[15];
    const float* W3l  = (const float*)d_in[16];
    const float* b3l  = (const float*)d_in[17];
    const float* W3g  = (const float*)d_in[18];
    const float* b3g  = (const float*)d_in[19];
    const float* Wlin = (const float*)d_in[20];
    const float* blin = (const float*)d_in[21];
    float* out = (float*)d_out;

    glimpse_kernel<<<NG, 256>>>(rgb, pos, pos1, pos2, idx0, idx1,
                                W1l, b1l, W1g, b1g, W2l, b2l, W2g, b2g, W3l, b3l);
    tail_kernel<<<NG / GPB, 256>>>(W3g, b3g, Wlin, blin, eps, out);
}

// round 7
// speedup vs baseline: 3.4059x; 1.3255x over previous
#include <cuda_runtime.h>
#include <cuda_bf16.h>

// Problem constants
#define NG        2048      // glimpses
#define NPG       512       // points per glimpse
#define CPG       128       // level-1 clusters per glimpse
#define CPG2      32        // level-2 clusters per glimpse

// branch-free fast celu: max(x,0) + expf(min(x,0)) - 1
__device__ __forceinline__ float celu1(float x) {
    return fmaxf(x, 0.f) + (__expf(fminf(x, 0.f)) - 1.f);
}

// scratch: per-glimpse stage-3 mean features [NG][128]  (1 MB)
__device__ float g_agg3m[NG * 128];

// ---------------------------------------------------------------------------
// Shared-memory layout (floats), total 14024 floats = 56096 B -> occ 4
// ---------------------------------------------------------------------------
#define OFF_POS1   0      // 384
#define OFF_POS2   384    // 96
#define OFF_W1L    480    // 64
#define OFF_B1L    544    // 16
#define OFF_W1G    560    // 512
#define OFF_B1G    1072   // 32
#define OFF_B2L    1104   // 64
#define OFF_B2G    1168   // 128
#define OFF_B3L    1296   // 128
#define OFF_AGG3   1424   // 128
#define OFF_S1     1552   // 128 int
#define OFF_SLOT   1680   // 128 int
#define OFF_SSEG   1808   // 128 int
#define OFF_OFF1   1936   // 128 int
#define OFF_OFF1F  2064   // 128 int
#define OFF_OFF2F  2192   // 32  int
#define OFF_CNT1   2224   // 128 int
#define OFF_CNT2   2352   // 32  int
#define OFF_A      2384   // 4620
#define OFF_D      7004   // 2304
#define OFF_C      9308   // 4716
#define SMEM_TOT   14024

__global__ __launch_bounds__(256, 4) void glimpse_kernel(
    const float* __restrict__ rgb,  const float* __restrict__ pos,
    const float* __restrict__ pos1, const float* __restrict__ pos2,
    const int* __restrict__ idx0, const int* __restrict__ idx1,
    const float* __restrict__ W1l, const float* __restrict__ b1l,
    const float* __restrict__ W1g, const float* __restrict__ b1g,
    const float* __restrict__ W2l, const float* __restrict__ b2l,
    const float* __restrict__ W2g, const float* __restrict__ b2g,
    const float* __restrict__ W3l, const float* __restrict__ b3l)
{
    __shared__ __align__(16) float sm[SMEM_TOT];
    int* smi = (int*)sm;

    float* pos1L = sm + OFF_POS1;
    float* pos2L = sm + OFF_POS2;
    float* W1lS  = sm + OFF_W1L;
    float* b1lS  = sm + OFF_B1L;
    float* W1gS  = sm + OFF_W1G;
    float* b1gS  = sm + OFF_B1G;
    float* b2lS  = sm + OFF_B2L;
    float* b2gS  = sm + OFF_B2G;
    float* b3lS  = sm + OFF_B3L;
    float* agg3  = sm + OFF_AGG3;
    int*   s1    = smi + OFF_S1;
    int*   slot  = smi + OFF_SLOT;
    int*   sseg  = smi + OFF_SSEG;
    int*   off1  = smi + OFF_OFF1;
    int*   off1f = smi + OFF_OFF1F;
    int*   off2f = smi + OFF_OFF2F;
    int*   cnt1i = smi + OFF_CNT1;
    int*   cnt2i = smi + OFF_CNT2;

    float* xT    = sm + OFF_A;            // [35][132]
    float* stX   = sm + OFF_A;            // [512]   staging (dead before xT written)
    float* stPx  = sm + OFF_A + 512;      // [512]
    float* stPy  = sm + OFF_A + 1024;     // [512]
    float* stPz  = sm + OFF_A + 1536;     // [512]
    int*   stS   = smi + OFF_A + 2048;    // [512]
    int*   plist = smi + OFF_A + 2560;    // [512]
    float* agg2T = sm + OFF_D;            // [64][36]
    float* agg1T = sm + OFF_C;            // [16][132]
    float* W2lS  = sm + OFF_C + 2112;     // [35][64]
    float* f2T   = sm + OFF_C;            // [131][36] (overwrites agg1T/W2lS later)

    const int t = threadIdx.x;
    const int g = blockIdx.x;

    // ---- block 0: loads + zeros ----
    for (int i = t; i < 384; i += 256) pos1L[i] = pos1[g * 384 + i];
    for (int i = t; i < 96;  i += 256) pos2L[i] = pos2[g * 96 + i];
    if (t < 64) { W1lS[t] = W1l[t]; b2lS[t] = b2l[t]; }
    if (t < 16) b1lS[t] = b1l[t];
    for (int i = t; i < 512; i += 256) W1gS[i] = W1g[i];
    if (t < 32) b1gS[t] = b1g[t];
    for (int i = t; i < 128; i += 256) { b2gS[i] = b2g[i]; b3lS[i] = b3l[i]; agg3[i] = 0.f; cnt1i[i] = 0; }
    if (t < 32) cnt2i[t] = 0;
    for (int i = t; i < 2112; i += 256) agg1T[i] = 0.f;
    for (int i = t; i < 2304; i += 256) agg2T[i] = 0.f;
    for (int i = t; i < 2240; i += 256) W2lS[i] = W2l[i];
    __syncthreads();

    // ---- block 1: stage points + counts ----
    for (int p = t; p < 512; p += 256) {
        stX[p] = rgb[g * 512 + p];
        int s = (idx0[g * 512 + p] - g * CPG) & (CPG - 1);
        stS[p] = s;
        atomicAdd(&cnt1i[s], 1);
    }
    for (int i = t; i < 1536; i += 256) {
        float v = pos[g * 1536 + i];
        int p = i / 3, c = i - p * 3;
        if (c == 0) stPx[p] = v; else if (c == 1) stPy[p] = v; else stPz[p] = v;
    }
    if (t < 128) {
        int s = (idx1[g * 128 + t] - g * CPG2) & (CPG2 - 1);
        s1[t] = s;
        atomicAdd(&cnt2i[s], 1);
    }
    __syncthreads();

    // ---- block 2: prefix sums (warp0: 128 seg counts; warp1: 32) ----
    if (t < 32) {
        int carry = 0;
        for (int c = 0; c < 4; c++) {
            int v = cnt1i[c * 32 + t];
            int x = v;
            #pragma unroll
            for (int d = 1; d < 32; d <<= 1) {
                int y = __shfl_up_sync(0xffffffffu, x, d);
                if (t >= d) x += y;
            }
            int excl = x - v + carry;
            off1[c * 32 + t] = excl;
            off1f[c * 32 + t] = excl;
            carry += __shfl_sync(0xffffffffu, x, 31);
        }
    } else if (t < 64) {
        int lane = t - 32;
        int v = cnt2i[lane];
        int x = v;
        #pragma unroll
        for (int d = 1; d < 32; d <<= 1) {
            int y = __shfl_up_sync(0xffffffffu, x, d);
            if (lane >= d) x += y;
        }
        off2f[lane] = x - v;
    }
    __syncthreads();

    // ---- block 3: scatter point list + row slots ----
    for (int p = t; p < 512; p += 256) {
        int s = stS[p];
        int pp = atomicAdd(&off1f[s], 1);
        plist[pp] = p;
    }
    if (t < 128) {
        int s = s1[t];
        int q = atomicAdd(&off2f[s], 1);
        slot[t] = q;
        sseg[q] = s;
    }
    __syncthreads();

    // ---- block 4: phase-1 accumulate (no feature atomics) + rel rows ----
    {
        int s = t >> 1, jb = (t & 1) * 8;
        int cnt = cnt1i[s], base = off1[s];
        float acc[8];
        #pragma unroll
        for (int j = 0; j < 8; j++) acc[j] = 0.f;
        const float c1x = pos1L[s * 3 + 0], c1y = pos1L[s * 3 + 1], c1z = pos1L[s * 3 + 2];
        for (int e = 0; e < cnt; e++) {
            int p = plist[base + e];
            float x0 = stX[p];
            float rx = stPx[p] - c1x, ry = stPy[p] - c1y, rz = stPz[p] - c1z;
            #pragma unroll
            for (int j = 0; j < 8; j++) {
                float h = b1lS[jb + j] + x0 * W1lS[jb + j] + rx * W1lS[16 + jb + j]
                        + ry * W1lS[32 + jb + j] + rz * W1lS[48 + jb + j];
                acc[j] += celu1(h);
            }
        }
        float inv = 1.f / (float)max(cnt, 1);
        #pragma unroll
        for (int j = 0; j < 8; j++) agg1T[(jb + j) * 132 + s] = acc[j] * inv;
    }
    for (int i = t; i < 384; i += 256) {
        int c = i >> 7, r = i & 127;
        int q = slot[r], s = s1[r];
        xT[(32 + c) * 132 + q] = pos1L[r * 3 + c] - pos2L[s * 3 + c];
    }
    __syncthreads();

    // ---- f1 GEMM: [128r x 16j] @ [16j x 32o] -> xT rows 0..31 at sorted slots
    {
        int ob = t & 7, rb = t >> 3;
        int r0 = rb * 4, o0 = ob * 4;
        float acc[4][4];
        #pragma unroll
        for (int ri = 0; ri < 4; ri++)
            #pragma unroll
            for (int oi = 0; oi < 4; oi++) acc[ri][oi] = b1gS[o0 + oi];
        #pragma unroll
        for (int j = 0; j < 16; j++) {
            float4 x = *(const float4*)&agg1T[j * 132 + r0];
            float4 w = *(const float4*)&W1gS[j * 32 + o0];
            float xa[4] = {x.x, x.y, x.z, x.w};
            float wa[4] = {w.x, w.y, w.z, w.w};
            #pragma unroll
            for (int ri = 0; ri < 4; ri++)
                #pragma unroll
                for (int oi = 0; oi < 4; oi++) acc[ri][oi] += xa[ri] * wa[oi];
        }
        int sl[4];
        #pragma unroll
        for (int ri = 0; ri < 4; ri++) sl[ri] = slot[r0 + ri];
        #pragma unroll
        for (int ri = 0; ri < 4; ri++)
            #pragma unroll
            for (int oi = 0; oi < 4; oi++)
                xT[(o0 + oi) * 132 + sl[ri]] = celu1(acc[ri][oi]);
    }
    __syncthreads();

    // ---- phase-2 edge GEMM: 128 rows (sorted) x [35 -> 64], run-merged atomics
    {
        int ob = t & 15, rb = t >> 4;
        int q0 = rb * 8, o0 = ob * 4;
        float acc[8][4];
        #pragma unroll
        for (int i = 0; i < 8; i++)
            #pragma unroll
            for (int oi = 0; oi < 4; oi++) acc[i][oi] = b2lS[o0 + oi];
        #pragma unroll 5
        for (int k = 0; k < 35; k++) {
            float4 xa4 = *(const float4*)&xT[k * 132 + q0];
            float4 xb4 = *(const float4*)&xT[k * 132 + q0 + 4];
            float4 w4  = *(const float4*)&W2lS[k * 64 + o0];
            float xa[8] = {xa4.x, xa4.y, xa4.z, xa4.w, xb4.x, xb4.y, xb4.z, xb4.w};
            float wa[4] = {w4.x, w4.y, w4.z, w4.w};
            #pragma unroll
            for (int i = 0; i < 8; i++)
                #pragma unroll
                for (int oi = 0; oi < 4; oi++) acc[i][oi] += xa[i] * wa[oi];
        }
        float run[4] = {0.f, 0.f, 0.f, 0.f};
        int curS = sseg[q0];
        #pragma unroll
        for (int i = 0; i < 8; i++) {
            int s = sseg[q0 + i];
            if (s != curS) {
                #pragma unroll
                for (int oi = 0; oi < 4; oi++) {
                    atomicAdd(&agg2T[(o0 + oi) * 36 + curS], run[oi]);
                    run[oi] = 0.f;
                }
                curS = s;
            }
            #pragma unroll
            for (int oi = 0; oi < 4; oi++) run[oi] += celu1(acc[i][oi]);
        }
        #pragma unroll
        for (int oi = 0; oi < 4; oi++) atomicAdd(&agg2T[(o0 + oi) * 36 + curS], run[oi]);
    }
    __syncthreads();

    // normalize agg2T
    for (int i = t; i < 2048; i += 256) {
        int j = i >> 5, s = i & 31;
        agg2T[j * 36 + s] *= 1.f / fmaxf((float)cnt2i[s], 1.f);
    }
    __syncthreads();

    // ---- f2 GEMM: [32s x 64j] @ W2g[64 x 128] -> f2T[128][32] (+pos2 rows)
    {
        int ob = t & 31, sb = t >> 5;
        int s0 = sb * 4, o0 = ob * 4;
        float acc[4][4];
        #pragma unroll
        for (int si = 0; si < 4; si++)
            #pragma unroll
            for (int oi = 0; oi < 4; oi++) acc[si][oi] = b2gS[o0 + oi];
        #pragma unroll 4
        for (int j = 0; j < 64; j++) {
            float4 x = *(const float4*)&agg2T[j * 36 + s0];
            float4 w = *(const float4*)&W2g[j * 128 + o0];
            float xa[4] = {x.x, x.y, x.z, x.w};
            float wa[4] = {w.x, w.y, w.z, w.w};
            #pragma unroll
            for (int si = 0; si < 4; si++)
                #pragma unroll
                for (int oi = 0; oi < 4; oi++) acc[si][oi] += xa[si] * wa[oi];
        }
        #pragma unroll
        for (int oi = 0; oi < 4; oi++)
            #pragma unroll
            for (int si = 0; si < 4; si++)
                f2T[(o0 + oi) * 36 + s0 + si] = celu1(acc[si][oi]);
    }
    if (t < 96) {
        int c = t >> 5, s = t & 31;
        f2T[(128 + c) * 36 + s] = pos2L[s * 3 + c];
    }
    __syncthreads();

    // ---- phase-3 GEMM: [32s x 131i] @ W3l[131 x 128] -> celu -> col-mean
    {
        int kb = t & 31, srb = t >> 5;
        int s0 = srb * 4, k0 = kb * 4;
        float acc[4][4];
        #pragma unroll
        for (int si = 0; si < 4; si++)
            #pragma unroll
            for (int ki = 0; ki < 4; ki++) acc[si][ki] = 0.f;
        #pragma unroll 4
        for (int i = 0; i < 131; i++) {
            float4 x = *(const float4*)&f2T[i * 36 + s0];
            float4 w = *(const float4*)&W3l[i * 128 + k0];
            float xa[4] = {x.x, x.y, x.z, x.w};
            float wa[4] = {w.x, w.y, w.z, w.w};
            #pragma unroll
            for (int si = 0; si < 4; si++)
                #pragma unroll
                for (int ki = 0; ki < 4; ki++) acc[si][ki] += xa[si] * wa[ki];
        }
        float part[4] = {0.f, 0.f, 0.f, 0.f};
        #pragma unroll
        for (int si = 0; si < 4; si++)
            #pragma unroll
            for (int ki = 0; ki < 4; ki++)
                part[ki] += celu1(acc[si][ki] + b3lS[k0 + ki]);
        #pragma unroll
        for (int ki = 0; ki < 4; ki++) atomicAdd(&agg3[k0 + ki], part[ki]);
    }
    __syncthreads();

    if (t < 128) g_agg3m[g * 128 + t] = agg3[t] * (1.f / 32.f);
}

// ---------------------------------------------------------------------------
// Tail: GPB=8 glimpses per CTA, 512 threads, K-split across two thread halves
// to double occupancy and memory-level parallelism.
//   f3 = celu(agg3m @ W3g + b3g); o = f3 @ Wlin + blin; split/softplus/sample.
// ---------------------------------------------------------------------------
#define GPB 8
__global__ __launch_bounds__(512) void tail_kernel(
    const float* __restrict__ W3g, const float* __restrict__ b3g,
    const float* __restrict__ Wlin, const float* __restrict__ blin,
    const float* __restrict__ eps, float* __restrict__ out)
{
    __shared__ __align__(16) float sAT[128 * GPB];   // [j][g]
    __shared__ __align__(16) float sP[512 * GPB];    // partial sums [half*256+o][g]
    __shared__ __align__(16) float sFT[256 * GPB];   // f3 [j][g]
    __shared__ __align__(16) float sO[256 * GPB];    // linear out [o][g]

    const int t    = threadIdx.x;
    const int o    = t & 255;
    const int half = t >> 8;
    const int g0   = blockIdx.x * GPB;

    for (int i = t; i < 128 * GPB; i += 512) {
        int j = i >> 3, gg = i & 7;
        sAT[j * 8 + gg] = g_agg3m[(g0 + gg) * 128 + j];
    }
    __syncthreads();

    // GEMM1: K=128 split into two 64-halves
    {
        float acc[8];
        #pragma unroll
        for (int gg = 0; gg < 8; gg++) acc[gg] = 0.f;
        const int jb = half * 64;
        #pragma unroll 4
        for (int jj = 0; jj < 64; jj++) {
            const int j = jb + jj;
            const float w = W3g[j * 256 + o];
            float4 a0 = *(const float4*)&sAT[j * 8];
            float4 a1 = *(const float4*)&sAT[j * 8 + 4];
            acc[0] += a0.x * w; acc[1] += a0.y * w; acc[2] += a0.z * w; acc[3] += a0.w * w;
            acc[4] += a1.x * w; acc[5] += a1.y * w; acc[6] += a1.z * w; acc[7] += a1.w * w;
        }
        #pragma unroll
        for (int gg = 0; gg < 8; gg++) sP[t * 8 + gg] = acc[gg];
    }
    __syncthreads();
    if (half == 0) {
        const float bo = b3g[o];
        #pragma unroll
        for (int gg = 0; gg < 8; gg++) {
            float v = celu1(sP[o * 8 + gg] + sP[(256 + o) * 8 + gg] + bo);
            sFT[o * 8 + gg] = v;
            out[786432 + (size_t)(g0 + gg) * 256 + o] = v;   // "f" output
        }
    }
    __syncthreads();

    // GEMM2: K=256 split into two 128-halves
    {
        float acc[8];
        #pragma unroll
        for (int gg = 0; gg < 8; gg++) acc[gg] = 0.f;
        const int jb = half * 128;
        #pragma unroll 4
        for (int jj = 0; jj < 128; jj++) {
            const int j = jb + jj;
            const float w = Wlin[j * 256 + o];
            float4 a0 = *(const float4*)&sFT[j * 8];
            float4 a1 = *(const float4*)&sFT[j * 8 + 4];
            acc[0] += a0.x * w; acc[1] += a0.y * w; acc[2] += a0.z * w; acc[3] += a0.w * w;
            acc[4] += a1.x * w; acc[5] += a1.y * w; acc[6] += a1.z * w; acc[7] += a1.w * w;
        }
        #pragma unroll
        for (int gg = 0; gg < 8; gg++) sP[t * 8 + gg] = acc[gg];
    }
    __syncthreads();
    if (half == 0) {
        const float bo = blin[o];
        #pragma unroll
        for (int gg = 0; gg < 8; gg++)
            sO[o * 8 + gg] = sP[o * 8 + gg] + sP[(256 + o) * 8 + gg] + bo;
    }
    __syncthreads();

    for (int i = t; i < 128 * GPB; i += 512) {
        int gg = i >> 7, c = i & 127;
        int gid = g0 + gg;
        float mu = sO[c * 8 + gg];
        float sg = sO[(128 + c) * 8 + gg];
        float sigma = (sg > 20.f) ? sg : log1pf(expf(sg));
        float z = mu + sigma * eps[gid * 128 + c];
        if (c < 64) out[(size_t)gid * 64 + c] = z;                      // z_what
        else        out[131072 + (size_t)gid * 64 + (c - 64)] = z;      // z_mask
        out[262144 + (size_t)gid * 128 + c] = mu;                       // mu
        out[524288 + (size_t)gid * 128 + c] = sigma;                    // sigma
    }
}

extern "C" void kernel_launch(void* const* d_in, const int* in_sizes, int n_in,
                              void* d_out, int out_size)
{
    (void)in_sizes; (void)n_in; (void)out_size;
    const float* rgb  = (const float*)d_in[0];
    const float* pos  = (const float*)d_in[1];
    const float* pos1 = (const float*)d_in[2];
    const float* pos2 = (const float*)d_in[3];
    const int*   idx0 = (const int*)d_in[4];
    const int*   idx1 = (const int*)d_in[5];
    // d_in[6] (out_index2) unused: structure is implied (32 pts/glimpse)
    const float* eps  = (const float*)d_in[7];
    const float* W1l  = (const float*)d_in[8];
    const float* b1l  = (const float*)d_in[9];
    const float* W1g  = (const float*)d_in[10];
    const float* b1g  = (const float*)d_in[11];
    const float* W2l  = (const float*)d_in[12];
    const float* b2l  = (const float*)d_in[13];
    const float* W2g  = (const float*)d_in[14];
    const float* b2g  = (const float*)d_in[15];
    const float* W3l  = (const float*)d_in[16];
    const float* b3l  = (const float*)d_in[17];
    const float* W3g  = (const float*)d_in[18];
    const float* b3g  = (const float*)d_in[19];
    const float* Wlin = (const float*)d_in[20];
    const float* blin = (const float*)d_in[21];
    float* out = (float*)d_out;

    glimpse_kernel<<<NG, 256>>>(rgb, pos, pos1, pos2, idx0, idx1,
                                W1l, b1l, W1g, b1g, W2l, b2l, W2g, b2g, W3l, b3l);
    tail_kernel<<<NG / GPB, 512>>>(W3g, b3g, Wlin, blin, eps, out);
}